// round 2
// baseline (speedup 1.0000x reference)
#include <cuda_runtime.h>
#include <math.h>

#define B_TOTAL 131072
#define Hh 128
#define Dd 256
#define Ee 128
#define G3H 384
#define MT 32
#define NTHR 256

typedef unsigned long long u64;

__device__ __forceinline__ u64 pack2(float lo, float hi) {
    u64 r;
    asm("mov.b64 %0,{%1,%2};" : "=l"(r)
        : "r"(__float_as_uint(lo)), "r"(__float_as_uint(hi)));
    return r;
}
__device__ __forceinline__ u64 bcast2(float x) {
    u64 r;
    asm("mov.b64 %0,{%1,%1};" : "=l"(r) : "r"(__float_as_uint(x)));
    return r;
}
__device__ __forceinline__ void ffma2(u64& d, u64 a, u64 b) {
    asm("fma.rn.f32x2 %0,%1,%2,%3;" : "=l"(d) : "l"(a), "l"(b), "l"(d));
}
__device__ __forceinline__ void unpk2(u64 v, float& a, float& b) {
    unsigned lo, hi;
    asm("mov.b64 {%0,%1},%2;" : "=r"(lo), "=r"(hi) : "l"(v));
    a = __uint_as_float(lo); b = __uint_as_float(hi);
}

// Transposed GRU weights (k-major [E][3H]) — device scratch, no allocation.
__device__ float g_wihT[Ee * G3H];
__device__ float g_whhT[Hh * G3H];

__global__ void transpose_gru_kernel(const float* __restrict__ wih,
                                     const float* __restrict__ whh) {
    int idx = blockIdx.x * blockDim.x + threadIdx.x;
    if (idx < Ee * G3H) {
        int e = idx / G3H, j = idx % G3H;
        g_wihT[idx] = wih[j * Ee + e];
        g_whhT[idx] = whh[j * Hh + e];
    }
}

// ---------------------------------------------------------------------------
// evolve: RK4(3/8). lane = row (32 rows/CTA), warp = column slice.
// mm1: warp owns 32 of 256 cols; mm2: warp owns 16 of 128 cols.
// Weight reads are warp-broadcast LDS; activation reads use padded strides.
// w2 staged per-CTA into double-buffered smem slabs (32 k-rows x 128 cols).
// ---------------------------------------------------------------------------
#define EV_SM_FLOATS 54720
__global__ void __launch_bounds__(NTHR, 1) evolve_kernel(
    const float* __restrict__ hidden, const float* __restrict__ dts,
    const float* __restrict__ w1, const float* __restrict__ b1,
    const float* __restrict__ lnw, const float* __restrict__ lnb,
    const float* __restrict__ w2, const float* __restrict__ b2,
    float* __restrict__ evolved)
{
    extern __shared__ float sm[];
    float* w1_s  = sm;              // 32768 : w1 [128][256], resident
    float* w2s   = sm + 32768;      // 8192  : 2 slabs of [32][128]
    float* arg_s = sm + 40960;      // 4128  : 32 x (128+1)
    float* a_s   = sm + 45088;      // 8224  : 32 x (256+1)
    float* red_s = sm + 53312;      // 512   : 2 x [8][32]
    float* p_b1  = sm + 53824;      // 256
    float* p_lnw = sm + 54080;      // 256
    float* p_lnb = sm + 54336;      // 256
    float* p_b2  = sm + 54592;      // 128

    const int tid  = threadIdx.x;
    const int lane = tid & 31;
    const int wrp  = tid >> 5;
    const int c1   = wrp * 32;      // mm1 col base
    const int c2   = wrp * 16;      // mm2 col base
    const size_t row0 = (size_t)blockIdx.x * MT;

    // ---- stage w1 + input tile + params ----
    {
        const float4* s4 = reinterpret_cast<const float4*>(w1);
        float4* d4 = reinterpret_cast<float4*>(w1_s);
        #pragma unroll
        for (int t = 0; t < 32; ++t) d4[tid + t * NTHR] = s4[tid + t * NTHR];
    }
    {
        const float4* s4 = reinterpret_cast<const float4*>(hidden + row0 * Hh);
        #pragma unroll
        for (int t = 0; t < 4; ++t) {
            int i4 = tid + t * NTHR;
            float4 v = s4[i4];
            int r = (i4 * 4) >> 7, c = (i4 * 4) & 127;
            float* d = arg_s + r * 129 + c;
            d[0] = v.x; d[1] = v.y; d[2] = v.z; d[3] = v.w;
        }
    }
    p_b1[tid]  = b1[tid];
    p_lnw[tid] = lnw[tid];
    p_lnb[tid] = lnb[tid];
    if (tid < 128) p_b2[tid] = b2[tid];

    // per-lane persistent state (lane = row)
    const float dtv = fmaxf(dts[row0 + lane], 0.0f);
    float hreg[16];
    {
        const float4* hp = reinterpret_cast<const float4*>(
            hidden + (row0 + lane) * Hh + c2);
        #pragma unroll
        for (int q = 0; q < 4; ++q) {
            float4 v = __ldg(hp + q);
            hreg[4 * q] = v.x; hreg[4 * q + 1] = v.y;
            hreg[4 * q + 2] = v.z; hreg[4 * q + 3] = v.w;
        }
    }
    __syncthreads();

    float k1a[16], k2a[16], acc[16];

    #pragma unroll 1
    for (int st = 0; st < 4; ++st) {
        // ================= mm1: u[row=lane][c1..c1+32) = arg @ w1 + b1 =====
        u64 u2[16];
        #pragma unroll
        for (int q = 0; q < 16; ++q)
            u2[q] = pack2(p_b1[c1 + 2 * q], p_b1[c1 + 2 * q + 1]);

        const float* argrow = arg_s + lane * 129;
        #pragma unroll 2
        for (int k = 0; k < Hh; ++k) {
            u64 aa = bcast2(argrow[k]);
            const ulonglong2* wv =
                reinterpret_cast<const ulonglong2*>(w1_s + k * Dd + c1);
            #pragma unroll
            for (int q = 0; q < 8; ++q) {
                ulonglong2 W = wv[q];
                ffma2(u2[2 * q],     aa, W.x);
                ffma2(u2[2 * q + 1], aa, W.y);
            }
        }

        // partial row sums -> red, prefetch w2 slab0
        {
            float s1 = 0.f, s2 = 0.f;
            #pragma unroll
            for (int q = 0; q < 16; ++q) {
                float x, y; unpk2(u2[q], x, y);
                s1 += x + y; s2 += x * x + y * y;
            }
            red_s[wrp * 32 + lane] = s1;
            red_s[256 + wrp * 32 + lane] = s2;
        }
        {
            const float4* src = reinterpret_cast<const float4*>(w2);
            float4* dst = reinterpret_cast<float4*>(w2s);
            #pragma unroll
            for (int t = 0; t < 4; ++t) dst[tid + t * NTHR] = src[tid + t * NTHR];
        }
        __syncthreads();

        // ================= LayerNorm + exact GELU -> a_s ====================
        {
            float t1 = 0.f, t2 = 0.f;
            #pragma unroll
            for (int w = 0; w < 8; ++w) {
                t1 += red_s[w * 32 + lane];
                t2 += red_s[256 + w * 32 + lane];
            }
            float mu   = t1 * (1.0f / Dd);
            float var  = t2 * (1.0f / Dd) - mu * mu;
            float rstd = rsqrtf(var + 1e-5f);
            float* arow = a_s + lane * 257 + c1;
            #pragma unroll
            for (int q = 0; q < 16; ++q) {
                float x, y; unpk2(u2[q], x, y);
                int c = c1 + 2 * q;
                float v0 = (x - mu) * rstd * p_lnw[c] + p_lnb[c];
                float v1 = (y - mu) * rstd * p_lnw[c + 1] + p_lnb[c + 1];
                arow[2 * q]     = v0 * normcdff(v0);
                arow[2 * q + 1] = v1 * normcdff(v1);
            }
        }
        __syncthreads();

        // ================= mm2: kv[row=lane][c2..c2+16) = a @ w2 + b2 ======
        u64 kv2[8];
        #pragma unroll
        for (int q = 0; q < 8; ++q)
            kv2[q] = pack2(p_b2[c2 + 2 * q], p_b2[c2 + 2 * q + 1]);

        const float* asrow = a_s + lane * 257;
        #pragma unroll 1
        for (int s8 = 0; s8 < 8; ++s8) {
            const float* cur = w2s + (s8 & 1) * 4096;
            if (s8 < 7) {
                const float4* src =
                    reinterpret_cast<const float4*>(w2) + (s8 + 1) * 1024;
                float4* dst = reinterpret_cast<float4*>(
                    w2s + ((s8 + 1) & 1) * 4096);
                #pragma unroll
                for (int t = 0; t < 4; ++t)
                    dst[tid + t * NTHR] = src[tid + t * NTHR];
            }
            #pragma unroll 4
            for (int kk = 0; kk < 32; ++kk) {
                u64 aa = bcast2(asrow[s8 * 32 + kk]);
                const ulonglong2* wv =
                    reinterpret_cast<const ulonglong2*>(cur + kk * Hh + c2);
                #pragma unroll
                for (int q = 0; q < 4; ++q) {
                    ulonglong2 W = wv[q];
                    ffma2(kv2[2 * q],     aa, W.x);
                    ffma2(kv2[2 * q + 1], aa, W.y);
                }
            }
            __syncthreads();
        }

        // ================= RK4 combine =====================================
        float kv[16];
        #pragma unroll
        for (int q = 0; q < 8; ++q) unpk2(kv2[q], kv[2 * q], kv[2 * q + 1]);

        float* argw = arg_s + lane * 129 + c2;
        if (st == 0) {
            #pragma unroll
            for (int j = 0; j < 16; ++j) {
                k1a[j] = kv[j]; acc[j] = kv[j];
                argw[j] = hreg[j] + dtv * (kv[j] * (1.0f / 3.0f));
            }
        } else if (st == 1) {
            #pragma unroll
            for (int j = 0; j < 16; ++j) {
                k2a[j] = kv[j]; acc[j] += 3.0f * kv[j];
                argw[j] = hreg[j] + dtv * (kv[j] - k1a[j] * (1.0f / 3.0f));
            }
        } else if (st == 2) {
            #pragma unroll
            for (int j = 0; j < 16; ++j) {
                acc[j] += 3.0f * kv[j];
                argw[j] = hreg[j] + dtv * (k1a[j] - k2a[j] + kv[j]);
            }
        } else {
            float4 ov[4];
            float* op = reinterpret_cast<float*>(ov);
            #pragma unroll
            for (int j = 0; j < 16; ++j) {
                float a = acc[j] + kv[j];
                op[j] = (dtv > 0.0f) ? (hreg[j] + dtv * a * 0.125f) : hreg[j];
            }
            float4* dst = reinterpret_cast<float4*>(
                evolved + (row0 + lane) * Hh + c2);
            #pragma unroll
            for (int q = 0; q < 4; ++q) dst[q] = ov[q];
        }
        if (st < 3) __syncthreads();
    }
}

// ---------------------------------------------------------------------------
// GRU. lane = row; warp owns 16 hidden indices (hb..hb+16) across all 3 gates.
// Weights streamed as 8 k-slabs (4 wihT + 4 whhT), double-buffered in smem.
// ---------------------------------------------------------------------------
#define GRU_SM_FLOATS 32832
__global__ void __launch_bounds__(NTHR, 1) gru_kernel(
    const float* __restrict__ evolved, const float* __restrict__ obs,
    const int* __restrict__ mask,
    const float* __restrict__ bih, const float* __restrict__ bhh,
    float* __restrict__ updated)
{
    extern __shared__ float sm[];
    float* wsl   = sm;              // 24576 : 2 slabs of [32][384]
    float* obs_s = sm + 24576;      // 4128  : 32 x 129
    float* ev_s  = sm + 28704;      // 4128

    const int tid  = threadIdx.x;
    const int lane = tid & 31;
    const int wrp  = tid >> 5;
    const int hb   = wrp * 16;
    const size_t row0 = (size_t)blockIdx.x * MT;

    // stage obs / evolved tiles (padded stride 129)
    {
        const float4* so = reinterpret_cast<const float4*>(obs + row0 * Ee);
        const float4* se = reinterpret_cast<const float4*>(evolved + row0 * Hh);
        #pragma unroll
        for (int t = 0; t < 4; ++t) {
            int i4 = tid + t * NTHR;
            int r = (i4 * 4) >> 7, c = (i4 * 4) & 127;
            float4 v = so[i4];
            float* d = obs_s + r * 129 + c;
            d[0] = v.x; d[1] = v.y; d[2] = v.z; d[3] = v.w;
            float4 u = se[i4];
            float* e = ev_s + r * 129 + c;
            e[0] = u.x; e[1] = u.y; e[2] = u.z; e[3] = u.w;
        }
    }
    // prefetch wihT slab 0
    {
        const float4* src = reinterpret_cast<const float4*>(g_wihT);
        float4* dst = reinterpret_cast<float4*>(wsl);
        #pragma unroll
        for (int t = 0; t < 12; ++t) dst[tid + t * NTHR] = src[tid + t * NTHR];
    }
    __syncthreads();

    // accumulators: gi2[g*8+q], gh2[g*8+q]
    u64 gi2[24], gh2[24];
    #pragma unroll
    for (int g = 0; g < 3; ++g)
        #pragma unroll
        for (int q = 0; q < 8; ++q) {
            int c = g * Hh + hb + 2 * q;
            gi2[g * 8 + q] = pack2(__ldg(bih + c), __ldg(bih + c + 1));
            gh2[g * 8 + q] = pack2(__ldg(bhh + c), __ldg(bhh + c + 1));
        }

    #pragma unroll 1
    for (int s = 0; s < 8; ++s) {
        const float* cur = wsl + (s & 1) * 12288;
        if (s < 7) {
            const float* gsrc = (s < 3) ? (g_wihT + (s + 1) * 12288)
                                        : (g_whhT + (s - 3) * 12288);
            const float4* src = reinterpret_cast<const float4*>(gsrc);
            float4* dst = reinterpret_cast<float4*>(wsl + ((s + 1) & 1) * 12288);
            #pragma unroll
            for (int t = 0; t < 12; ++t)
                dst[tid + t * NTHR] = src[tid + t * NTHR];
        }
        const float* arow = ((s < 4) ? obs_s : ev_s) + lane * 129 + (s & 3) * 32;
        u64* accp = (s < 4) ? gi2 : gh2;
        #pragma unroll 2
        for (int kk = 0; kk < 32; ++kk) {
            u64 aa = bcast2(arow[kk]);
            #pragma unroll
            for (int g = 0; g < 3; ++g) {
                const ulonglong2* wv = reinterpret_cast<const ulonglong2*>(
                    cur + kk * G3H + g * Hh + hb);
                #pragma unroll
                for (int q = 0; q < 4; ++q) {
                    ulonglong2 W = wv[q];
                    ffma2(accp[g * 8 + 2 * q],     aa, W.x);
                    ffma2(accp[g * 8 + 2 * q + 1], aa, W.y);
                }
            }
        }
        __syncthreads();
    }

    // gates + select
    const int msk = __ldg(mask + row0 + lane);
    const float* evrow = ev_s + lane * 129 + hb;
    float outv[16];
    #pragma unroll
    for (int q = 0; q < 8; ++q) {
        float ir0, ir1, iz0, iz1, in0, in1;
        float hr0, hr1, hz0, hz1, hn0, hn1;
        unpk2(gi2[q],      ir0, ir1);
        unpk2(gi2[8 + q],  iz0, iz1);
        unpk2(gi2[16 + q], in0, in1);
        unpk2(gh2[q],      hr0, hr1);
        unpk2(gh2[8 + q],  hz0, hz1);
        unpk2(gh2[16 + q], hn0, hn1);

        float r0 = 1.0f / (1.0f + __expf(-(ir0 + hr0)));
        float z0 = 1.0f / (1.0f + __expf(-(iz0 + hz0)));
        float n0 = tanhf(in0 + r0 * hn0);
        float e0 = evrow[2 * q];
        outv[2 * q] = (msk > 0) ? ((1.0f - z0) * n0 + z0 * e0) : e0;

        float r1 = 1.0f / (1.0f + __expf(-(ir1 + hr1)));
        float z1 = 1.0f / (1.0f + __expf(-(iz1 + hz1)));
        float n1 = tanhf(in1 + r1 * hn1);
        float e1 = evrow[2 * q + 1];
        outv[2 * q + 1] = (msk > 0) ? ((1.0f - z1) * n1 + z1 * e1) : e1;
    }
    float4* dst = reinterpret_cast<float4*>(updated + (row0 + lane) * Hh + hb);
    const float4* sv = reinterpret_cast<const float4*>(outv);
    #pragma unroll
    for (int q = 0; q < 4; ++q) dst[q] = sv[q];
}

// ---------------------------------------------------------------------------
extern "C" void kernel_launch(void* const* d_in, const int* in_sizes, int n_in,
                              void* d_out, int out_size)
{
    const float* hidden = (const float*)d_in[0];
    const float* dts    = (const float*)d_in[1];
    const float* obs    = (const float*)d_in[2];
    const int*   mask   = (const int*)d_in[3];
    const float* w1     = (const float*)d_in[4];
    const float* b1     = (const float*)d_in[5];
    const float* lnw    = (const float*)d_in[6];
    const float* lnb    = (const float*)d_in[7];
    const float* w2     = (const float*)d_in[8];
    const float* b2     = (const float*)d_in[9];
    const float* wih    = (const float*)d_in[10];
    const float* whh    = (const float*)d_in[11];
    const float* bih    = (const float*)d_in[12];
    const float* bhh    = (const float*)d_in[13];

    float* evolved = (float*)d_out;
    float* updated = evolved + (size_t)B_TOTAL * Hh;

    cudaFuncSetAttribute(evolve_kernel, cudaFuncAttributeMaxDynamicSharedMemorySize,
                         EV_SM_FLOATS * 4);
    cudaFuncSetAttribute(gru_kernel, cudaFuncAttributeMaxDynamicSharedMemorySize,
                         GRU_SM_FLOATS * 4);

    transpose_gru_kernel<<<(Ee * G3H + 255) / 256, 256>>>(wih, whh);
    evolve_kernel<<<B_TOTAL / MT, NTHR, EV_SM_FLOATS * 4>>>(
        hidden, dts, w1, b1, lnw, lnb, w2, b2, evolved);
    gru_kernel<<<B_TOTAL / MT, NTHR, GRU_SM_FLOATS * 4>>>(
        evolved, obs, mask, bih, bhh, updated);
}

// round 3
// speedup vs baseline: 1.0007x; 1.0007x over previous
#include <cuda_runtime.h>
#include <math.h>

#define B_TOTAL 131072
#define Hh 128
#define Dd 256
#define Ee 128
#define G3H 384
#define MT 32
#define NTHR 256

typedef unsigned long long u64;

__device__ __forceinline__ u64 pack2(float lo, float hi) {
    u64 r;
    asm("mov.b64 %0,{%1,%2};" : "=l"(r)
        : "r"(__float_as_uint(lo)), "r"(__float_as_uint(hi)));
    return r;
}
__device__ __forceinline__ u64 bcast2(float x) {
    u64 r;
    asm("mov.b64 %0,{%1,%1};" : "=l"(r) : "r"(__float_as_uint(x)));
    return r;
}
__device__ __forceinline__ void ffma2(u64& d, u64 a, u64 b) {
    asm("fma.rn.f32x2 %0,%1,%2,%3;" : "=l"(d) : "l"(a), "l"(b), "l"(d));
}
__device__ __forceinline__ void unpk2(u64 v, float& a, float& b) {
    unsigned lo, hi;
    asm("mov.b64 {%0,%1},%2;" : "=r"(lo), "=r"(hi) : "l"(v));
    a = __uint_as_float(lo); b = __uint_as_float(hi);
}

// Transposed GRU weights (k-major [E][3H]) — device scratch, no allocation.
__device__ float g_wihT[Ee * G3H];
__device__ float g_whhT[Hh * G3H];

__global__ void transpose_gru_kernel(const float* __restrict__ wih,
                                     const float* __restrict__ whh) {
    int idx = blockIdx.x * blockDim.x + threadIdx.x;
    if (idx < Ee * G3H) {
        int e = idx / G3H, j = idx % G3H;
        g_wihT[idx] = wih[j * Ee + e];
        g_whhT[idx] = whh[j * Hh + e];
    }
}

// ---------------------------------------------------------------------------
// evolve: RK4(3/8). lane = row (32 rows/CTA), warp = column slice.
// mm1: warp owns 32 of 256 cols; mm2: warp owns 16 of 128 cols.
// Weight reads are warp-broadcast LDS; activation reads use padded strides.
// w2 staged per-CTA into double-buffered smem slabs (32 k-rows x 128 cols).
// ---------------------------------------------------------------------------
#define EV_SM_FLOATS 54720
__global__ void __launch_bounds__(NTHR, 1) evolve_kernel(
    const float* __restrict__ hidden, const float* __restrict__ dts,
    const float* __restrict__ w1, const float* __restrict__ b1,
    const float* __restrict__ lnw, const float* __restrict__ lnb,
    const float* __restrict__ w2, const float* __restrict__ b2,
    float* __restrict__ evolved)
{
    extern __shared__ float sm[];
    float* w1_s  = sm;              // 32768 : w1 [128][256], resident
    float* w2s   = sm + 32768;      // 8192  : 2 slabs of [32][128]
    float* arg_s = sm + 40960;      // 4128  : 32 x (128+1)
    float* a_s   = sm + 45088;      // 8224  : 32 x (256+1)
    float* red_s = sm + 53312;      // 512   : 2 x [8][32]
    float* p_b1  = sm + 53824;      // 256
    float* p_lnw = sm + 54080;      // 256
    float* p_lnb = sm + 54336;      // 256
    float* p_b2  = sm + 54592;      // 128

    const int tid  = threadIdx.x;
    const int lane = tid & 31;
    const int wrp  = tid >> 5;
    const int c1   = wrp * 32;      // mm1 col base
    const int c2   = wrp * 16;      // mm2 col base
    const size_t row0 = (size_t)blockIdx.x * MT;

    // ---- stage w1 + input tile + params ----
    {
        const float4* s4 = reinterpret_cast<const float4*>(w1);
        float4* d4 = reinterpret_cast<float4*>(w1_s);
        #pragma unroll
        for (int t = 0; t < 32; ++t) d4[tid + t * NTHR] = s4[tid + t * NTHR];
    }
    {
        const float4* s4 = reinterpret_cast<const float4*>(hidden + row0 * Hh);
        #pragma unroll
        for (int t = 0; t < 4; ++t) {
            int i4 = tid + t * NTHR;
            float4 v = s4[i4];
            int r = (i4 * 4) >> 7, c = (i4 * 4) & 127;
            float* d = arg_s + r * 129 + c;
            d[0] = v.x; d[1] = v.y; d[2] = v.z; d[3] = v.w;
        }
    }
    p_b1[tid]  = b1[tid];
    p_lnw[tid] = lnw[tid];
    p_lnb[tid] = lnb[tid];
    if (tid < 128) p_b2[tid] = b2[tid];

    // per-lane persistent state (lane = row)
    const float dtv = fmaxf(dts[row0 + lane], 0.0f);
    float hreg[16];
    {
        const float4* hp = reinterpret_cast<const float4*>(
            hidden + (row0 + lane) * Hh + c2);
        #pragma unroll
        for (int q = 0; q < 4; ++q) {
            float4 v = __ldg(hp + q);
            hreg[4 * q] = v.x; hreg[4 * q + 1] = v.y;
            hreg[4 * q + 2] = v.z; hreg[4 * q + 3] = v.w;
        }
    }
    __syncthreads();

    float k1a[16], k2a[16], acc[16];

    #pragma unroll 1
    for (int st = 0; st < 4; ++st) {
        // ================= mm1: u[row=lane][c1..c1+32) = arg @ w1 + b1 =====
        u64 u2[16];
        #pragma unroll
        for (int q = 0; q < 16; ++q)
            u2[q] = pack2(p_b1[c1 + 2 * q], p_b1[c1 + 2 * q + 1]);

        const float* argrow = arg_s + lane * 129;
        #pragma unroll 2
        for (int k = 0; k < Hh; ++k) {
            u64 aa = bcast2(argrow[k]);
            const ulonglong2* wv =
                reinterpret_cast<const ulonglong2*>(w1_s + k * Dd + c1);
            #pragma unroll
            for (int q = 0; q < 8; ++q) {
                ulonglong2 W = wv[q];
                ffma2(u2[2 * q],     aa, W.x);
                ffma2(u2[2 * q + 1], aa, W.y);
            }
        }

        // partial row sums -> red, prefetch w2 slab0
        {
            float s1 = 0.f, s2 = 0.f;
            #pragma unroll
            for (int q = 0; q < 16; ++q) {
                float x, y; unpk2(u2[q], x, y);
                s1 += x + y; s2 += x * x + y * y;
            }
            red_s[wrp * 32 + lane] = s1;
            red_s[256 + wrp * 32 + lane] = s2;
        }
        {
            const float4* src = reinterpret_cast<const float4*>(w2);
            float4* dst = reinterpret_cast<float4*>(w2s);
            #pragma unroll
            for (int t = 0; t < 4; ++t) dst[tid + t * NTHR] = src[tid + t * NTHR];
        }
        __syncthreads();

        // ================= LayerNorm + exact GELU -> a_s ====================
        {
            float t1 = 0.f, t2 = 0.f;
            #pragma unroll
            for (int w = 0; w < 8; ++w) {
                t1 += red_s[w * 32 + lane];
                t2 += red_s[256 + w * 32 + lane];
            }
            float mu   = t1 * (1.0f / Dd);
            float var  = t2 * (1.0f / Dd) - mu * mu;
            float rstd = rsqrtf(var + 1e-5f);
            float* arow = a_s + lane * 257 + c1;
            #pragma unroll
            for (int q = 0; q < 16; ++q) {
                float x, y; unpk2(u2[q], x, y);
                int c = c1 + 2 * q;
                float v0 = (x - mu) * rstd * p_lnw[c] + p_lnb[c];
                float v1 = (y - mu) * rstd * p_lnw[c + 1] + p_lnb[c + 1];
                arow[2 * q]     = v0 * normcdff(v0);
                arow[2 * q + 1] = v1 * normcdff(v1);
            }
        }
        __syncthreads();

        // ================= mm2: kv[row=lane][c2..c2+16) = a @ w2 + b2 ======
        u64 kv2[8];
        #pragma unroll
        for (int q = 0; q < 8; ++q)
            kv2[q] = pack2(p_b2[c2 + 2 * q], p_b2[c2 + 2 * q + 1]);

        const float* asrow = a_s + lane * 257;
        #pragma unroll 1
        for (int s8 = 0; s8 < 8; ++s8) {
            const float* cur = w2s + (s8 & 1) * 4096;
            if (s8 < 7) {
                const float4* src =
                    reinterpret_cast<const float4*>(w2) + (s8 + 1) * 1024;
                float4* dst = reinterpret_cast<float4*>(
                    w2s + ((s8 + 1) & 1) * 4096);
                #pragma unroll
                for (int t = 0; t < 4; ++t)
                    dst[tid + t * NTHR] = src[tid + t * NTHR];
            }
            #pragma unroll 4
            for (int kk = 0; kk < 32; ++kk) {
                u64 aa = bcast2(asrow[s8 * 32 + kk]);
                const ulonglong2* wv =
                    reinterpret_cast<const ulonglong2*>(cur + kk * Hh + c2);
                #pragma unroll
                for (int q = 0; q < 4; ++q) {
                    ulonglong2 W = wv[q];
                    ffma2(kv2[2 * q],     aa, W.x);
                    ffma2(kv2[2 * q + 1], aa, W.y);
                }
            }
            __syncthreads();
        }

        // ================= RK4 combine =====================================
        float kv[16];
        #pragma unroll
        for (int q = 0; q < 8; ++q) unpk2(kv2[q], kv[2 * q], kv[2 * q + 1]);

        float* argw = arg_s + lane * 129 + c2;
        if (st == 0) {
            #pragma unroll
            for (int j = 0; j < 16; ++j) {
                k1a[j] = kv[j]; acc[j] = kv[j];
                argw[j] = hreg[j] + dtv * (kv[j] * (1.0f / 3.0f));
            }
        } else if (st == 1) {
            #pragma unroll
            for (int j = 0; j < 16; ++j) {
                k2a[j] = kv[j]; acc[j] += 3.0f * kv[j];
                argw[j] = hreg[j] + dtv * (kv[j] - k1a[j] * (1.0f / 3.0f));
            }
        } else if (st == 2) {
            #pragma unroll
            for (int j = 0; j < 16; ++j) {
                acc[j] += 3.0f * kv[j];
                argw[j] = hreg[j] + dtv * (k1a[j] - k2a[j] + kv[j]);
            }
        } else {
            float4 ov[4];
            float* op = reinterpret_cast<float*>(ov);
            #pragma unroll
            for (int j = 0; j < 16; ++j) {
                float a = acc[j] + kv[j];
                op[j] = (dtv > 0.0f) ? (hreg[j] + dtv * a * 0.125f) : hreg[j];
            }
            float4* dst = reinterpret_cast<float4*>(
                evolved + (row0 + lane) * Hh + c2);
            #pragma unroll
            for (int q = 0; q < 4; ++q) dst[q] = ov[q];
        }
        if (st < 3) __syncthreads();
    }
}

// ---------------------------------------------------------------------------
// GRU. lane = row; warp owns 16 hidden indices (hb..hb+16) across all 3 gates.
// Weights streamed as 8 k-slabs (4 wihT + 4 whhT), double-buffered in smem.
// ---------------------------------------------------------------------------
#define GRU_SM_FLOATS 32832
__global__ void __launch_bounds__(NTHR, 1) gru_kernel(
    const float* __restrict__ evolved, const float* __restrict__ obs,
    const int* __restrict__ mask,
    const float* __restrict__ bih, const float* __restrict__ bhh,
    float* __restrict__ updated)
{
    extern __shared__ float sm[];
    float* wsl   = sm;              // 24576 : 2 slabs of [32][384]
    float* obs_s = sm + 24576;      // 4128  : 32 x 129
    float* ev_s  = sm + 28704;      // 4128

    const int tid  = threadIdx.x;
    const int lane = tid & 31;
    const int wrp  = tid >> 5;
    const int hb   = wrp * 16;
    const size_t row0 = (size_t)blockIdx.x * MT;

    // stage obs / evolved tiles (padded stride 129)
    {
        const float4* so = reinterpret_cast<const float4*>(obs + row0 * Ee);
        const float4* se = reinterpret_cast<const float4*>(evolved + row0 * Hh);
        #pragma unroll
        for (int t = 0; t < 4; ++t) {
            int i4 = tid + t * NTHR;
            int r = (i4 * 4) >> 7, c = (i4 * 4) & 127;
            float4 v = so[i4];
            float* d = obs_s + r * 129 + c;
            d[0] = v.x; d[1] = v.y; d[2] = v.z; d[3] = v.w;
            float4 u = se[i4];
            float* e = ev_s + r * 129 + c;
            e[0] = u.x; e[1] = u.y; e[2] = u.z; e[3] = u.w;
        }
    }
    // prefetch wihT slab 0
    {
        const float4* src = reinterpret_cast<const float4*>(g_wihT);
        float4* dst = reinterpret_cast<float4*>(wsl);
        #pragma unroll
        for (int t = 0; t < 12; ++t) dst[tid + t * NTHR] = src[tid + t * NTHR];
    }
    __syncthreads();

    // accumulators: gi2[g*8+q], gh2[g*8+q]
    u64 gi2[24], gh2[24];
    #pragma unroll
    for (int g = 0; g < 3; ++g)
        #pragma unroll
        for (int q = 0; q < 8; ++q) {
            int c = g * Hh + hb + 2 * q;
            gi2[g * 8 + q] = pack2(__ldg(bih + c), __ldg(bih + c + 1));
            gh2[g * 8 + q] = pack2(__ldg(bhh + c), __ldg(bhh + c + 1));
        }

    #pragma unroll 1
    for (int s = 0; s < 8; ++s) {
        const float* cur = wsl + (s & 1) * 12288;
        if (s < 7) {
            const float* gsrc = (s < 3) ? (g_wihT + (s + 1) * 12288)
                                        : (g_whhT + (s - 3) * 12288);
            const float4* src = reinterpret_cast<const float4*>(gsrc);
            float4* dst = reinterpret_cast<float4*>(wsl + ((s + 1) & 1) * 12288);
            #pragma unroll
            for (int t = 0; t < 12; ++t)
                dst[tid + t * NTHR] = src[tid + t * NTHR];
        }
        const float* arow = ((s < 4) ? obs_s : ev_s) + lane * 129 + (s & 3) * 32;
        u64* accp = (s < 4) ? gi2 : gh2;
        #pragma unroll 2
        for (int kk = 0; kk < 32; ++kk) {
            u64 aa = bcast2(arow[kk]);
            #pragma unroll
            for (int g = 0; g < 3; ++g) {
                const ulonglong2* wv = reinterpret_cast<const ulonglong2*>(
                    cur + kk * G3H + g * Hh + hb);
                #pragma unroll
                for (int q = 0; q < 4; ++q) {
                    ulonglong2 W = wv[q];
                    ffma2(accp[g * 8 + 2 * q],     aa, W.x);
                    ffma2(accp[g * 8 + 2 * q + 1], aa, W.y);
                }
            }
        }
        __syncthreads();
    }

    // gates + select
    const int msk = __ldg(mask + row0 + lane);
    const float* evrow = ev_s + lane * 129 + hb;
    float outv[16];
    #pragma unroll
    for (int q = 0; q < 8; ++q) {
        float ir0, ir1, iz0, iz1, in0, in1;
        float hr0, hr1, hz0, hz1, hn0, hn1;
        unpk2(gi2[q],      ir0, ir1);
        unpk2(gi2[8 + q],  iz0, iz1);
        unpk2(gi2[16 + q], in0, in1);
        unpk2(gh2[q],      hr0, hr1);
        unpk2(gh2[8 + q],  hz0, hz1);
        unpk2(gh2[16 + q], hn0, hn1);

        float r0 = 1.0f / (1.0f + __expf(-(ir0 + hr0)));
        float z0 = 1.0f / (1.0f + __expf(-(iz0 + hz0)));
        float n0 = tanhf(in0 + r0 * hn0);
        float e0 = evrow[2 * q];
        outv[2 * q] = (msk > 0) ? ((1.0f - z0) * n0 + z0 * e0) : e0;

        float r1 = 1.0f / (1.0f + __expf(-(ir1 + hr1)));
        float z1 = 1.0f / (1.0f + __expf(-(iz1 + hz1)));
        float n1 = tanhf(in1 + r1 * hn1);
        float e1 = evrow[2 * q + 1];
        outv[2 * q + 1] = (msk > 0) ? ((1.0f - z1) * n1 + z1 * e1) : e1;
    }
    float4* dst = reinterpret_cast<float4*>(updated + (row0 + lane) * Hh + hb);
    const float4* sv = reinterpret_cast<const float4*>(outv);
    #pragma unroll
    for (int q = 0; q < 4; ++q) dst[q] = sv[q];
}

// ---------------------------------------------------------------------------
extern "C" void kernel_launch(void* const* d_in, const int* in_sizes, int n_in,
                              void* d_out, int out_size)
{
    const float* hidden = (const float*)d_in[0];
    const float* dts    = (const float*)d_in[1];
    const float* obs    = (const float*)d_in[2];
    const int*   mask   = (const int*)d_in[3];
    const float* w1     = (const float*)d_in[4];
    const float* b1     = (const float*)d_in[5];
    const float* lnw    = (const float*)d_in[6];
    const float* lnb    = (const float*)d_in[7];
    const float* w2     = (const float*)d_in[8];
    const float* b2     = (const float*)d_in[9];
    const float* wih    = (const float*)d_in[10];
    const float* whh    = (const float*)d_in[11];
    const float* bih    = (const float*)d_in[12];
    const float* bhh    = (const float*)d_in[13];

    float* evolved = (float*)d_out;
    float* updated = evolved + (size_t)B_TOTAL * Hh;

    cudaFuncSetAttribute(evolve_kernel, cudaFuncAttributeMaxDynamicSharedMemorySize,
                         EV_SM_FLOATS * 4);
    cudaFuncSetAttribute(gru_kernel, cudaFuncAttributeMaxDynamicSharedMemorySize,
                         GRU_SM_FLOATS * 4);

    transpose_gru_kernel<<<(Ee * G3H + 255) / 256, 256>>>(wih, whh);
    evolve_kernel<<<B_TOTAL / MT, NTHR, EV_SM_FLOATS * 4>>>(
        hidden, dts, w1, b1, lnw, lnb, w2, b2, evolved);
    gru_kernel<<<B_TOTAL / MT, NTHR, GRU_SM_FLOATS * 4>>>(
        evolved, obs, mask, bih, bhh, updated);
}

// round 4
// speedup vs baseline: 1.3112x; 1.3104x over previous
#include <cuda_runtime.h>
#include <math.h>

#define B_TOTAL 131072
#define Hh 128
#define Dd 256
#define Ee 128
#define G3H 384
#define MT 32
#define NTHR 256

typedef unsigned long long u64;

__device__ __forceinline__ u64 pack2(float lo, float hi) {
    u64 r;
    asm("mov.b64 %0,{%1,%2};" : "=l"(r)
        : "r"(__float_as_uint(lo)), "r"(__float_as_uint(hi)));
    return r;
}
__device__ __forceinline__ u64 bcast2(float x) {
    u64 r;
    asm("mov.b64 %0,{%1,%1};" : "=l"(r) : "r"(__float_as_uint(x)));
    return r;
}
__device__ __forceinline__ void ffma2(u64& d, u64 a, u64 b) {
    asm("fma.rn.f32x2 %0,%1,%2,%3;" : "=l"(d) : "l"(a), "l"(b), "l"(d));
}
__device__ __forceinline__ void unpk2(u64 v, float& a, float& b) {
    unsigned lo, hi;
    asm("mov.b64 {%0,%1},%2;" : "=r"(lo), "=r"(hi) : "l"(v));
    a = __uint_as_float(lo); b = __uint_as_float(hi);
}

// Transposed GRU weights (k-major [E][3H]) — device scratch, no allocation.
__device__ float g_wihT[Ee * G3H];
__device__ float g_whhT[Hh * G3H];

__global__ void transpose_gru_kernel(const float* __restrict__ wih,
                                     const float* __restrict__ whh) {
    int idx = blockIdx.x * blockDim.x + threadIdx.x;
    if (idx < Ee * G3H) {
        int e = idx / G3H, j = idx % G3H;
        g_wihT[idx] = wih[j * Ee + e];
        g_whhT[idx] = whh[j * Hh + e];
    }
}

// ---------------------------------------------------------------------------
// evolve: one RK4 (3/8 rule) step per row. 32 rows/CTA, 8 warps, 4 rows/warp.
// Round-1 structure (warp-private smem rows, no in-loop block barriers except
// one alignment barrier per stage before mm2), FFMA2-packed inner loops.
// ---------------------------------------------------------------------------
#define EV_SMEM_FLOATS 50080
__global__ void __launch_bounds__(NTHR, 1) evolve_kernel(
    const float* __restrict__ hidden, const float* __restrict__ dts,
    const float* __restrict__ w1, const float* __restrict__ b1,
    const float* __restrict__ lnw, const float* __restrict__ lnb,
    const float* __restrict__ w2, const float* __restrict__ b2,
    float* __restrict__ evolved)
{
    extern __shared__ float sm[];
    float* w1_s  = sm;              // 32768 floats (128KB), resident
    float* h_s   = sm + 32768;      // 32x128
    float* arg_s = sm + 36864;      // 32x128
    float* a_s   = sm + 40960;      // 32x256
    float* b1_s  = sm + 49152;      // 256
    float* lnw_s = sm + 49408;      // 256
    float* lnb_s = sm + 49664;      // 256
    float* b2_s  = sm + 49920;      // 128
    float* dt_s  = sm + 50048;      // 32

    const int tid  = threadIdx.x;
    const int lane = tid & 31;
    const int wrp  = tid >> 5;
    const int r0   = wrp * 4;                       // local row base (4 rows/warp)
    const size_t row0 = (size_t)blockIdx.x * MT;

    // ---- stage weights + tile ----
    {
        const float4* src = reinterpret_cast<const float4*>(w1);
        float4* dst = reinterpret_cast<float4*>(w1_s);
        #pragma unroll
        for (int t = 0; t < 32; ++t) dst[tid + t * NTHR] = src[tid + t * NTHR];
    }
    {
        const float4* src = reinterpret_cast<const float4*>(hidden + row0 * Hh);
        float4* dh = reinterpret_cast<float4*>(h_s);
        float4* da = reinterpret_cast<float4*>(arg_s);
        #pragma unroll
        for (int t = 0; t < 4; ++t) {
            float4 v = src[tid + t * NTHR];
            dh[tid + t * NTHR] = v;
            da[tid + t * NTHR] = v;
        }
    }
    if (tid < 256) { b1_s[tid] = b1[tid]; lnw_s[tid] = lnw[tid]; lnb_s[tid] = lnb[tid]; }
    if (tid < 128) b2_s[tid] = b2[tid];
    if (tid < 32)  dt_s[tid] = fmaxf(dts[row0 + tid], 0.0f);
    __syncthreads();

    float k1r[4][4], k2r[4][4], accr[4][4];

    #pragma unroll 1
    for (int s = 0; s < 4; ++s) {
        // ---- mm1: u[4 rows][8 cols] = arg @ w1 + b1 (FFMA2-packed) ----
        u64 u2[4][4];
        #pragma unroll
        for (int i = 0; i < 4; ++i)
            #pragma unroll
            for (int p = 0; p < 4; ++p)
                u2[i][p] = pack2(b1_s[lane * 8 + 2 * p], b1_s[lane * 8 + 2 * p + 1]);

        const ulonglong2* w1u = reinterpret_cast<const ulonglong2*>(w1_s);
        #pragma unroll 2
        for (int k = 0; k < Hh; k += 4) {
            float4 av[4];
            #pragma unroll
            for (int i = 0; i < 4; ++i)
                av[i] = *reinterpret_cast<const float4*>(arg_s + (r0 + i) * Hh + k);
            #pragma unroll
            for (int kk = 0; kk < 4; ++kk) {
                ulonglong2 W0 = w1u[(k + kk) * 64 + lane * 2];
                ulonglong2 W1 = w1u[(k + kk) * 64 + lane * 2 + 1];
                #pragma unroll
                for (int i = 0; i < 4; ++i) {
                    float a = (kk == 0) ? av[i].x : (kk == 1) ? av[i].y
                            : (kk == 2) ? av[i].z : av[i].w;
                    u64 aa = bcast2(a);
                    ffma2(u2[i][0], aa, W0.x);
                    ffma2(u2[i][1], aa, W0.y);
                    ffma2(u2[i][2], aa, W1.x);
                    ffma2(u2[i][3], aa, W1.y);
                }
            }
        }

        // ---- LayerNorm + exact GELU, a -> smem ----
        #pragma unroll
        for (int i = 0; i < 4; ++i) {
            float uv[8];
            #pragma unroll
            for (int p = 0; p < 4; ++p) unpk2(u2[i][p], uv[2 * p], uv[2 * p + 1]);
            float s1 = 0.f, s2 = 0.f;
            #pragma unroll
            for (int j = 0; j < 8; ++j) { s1 += uv[j]; s2 += uv[j] * uv[j]; }
            #pragma unroll
            for (int off = 16; off >= 1; off >>= 1) {
                s1 += __shfl_xor_sync(0xffffffffu, s1, off);
                s2 += __shfl_xor_sync(0xffffffffu, s2, off);
            }
            float mu   = s1 * (1.0f / Dd);
            float var  = s2 * (1.0f / Dd) - mu * mu;
            float rstd = rsqrtf(var + 1e-5f);
            #pragma unroll
            for (int j = 0; j < 8; ++j) {
                int c = lane * 8 + j;
                float v = (uv[j] - mu) * rstd * lnw_s[c] + lnb_s[c];
                a_s[(r0 + i) * Dd + c] = v * normcdff(v);   // exact gelu
            }
        }
        // align warps so the 8-warp shared w2 L2 stream dedups in L1
        __syncthreads();

        // ---- mm2: kv[4 rows][4 cols] = a @ w2 + b2 (w2 streamed, FFMA2) ----
        u64 kv2[4][2];
        #pragma unroll
        for (int i = 0; i < 4; ++i) {
            kv2[i][0] = pack2(b2_s[lane * 4],     b2_s[lane * 4 + 1]);
            kv2[i][1] = pack2(b2_s[lane * 4 + 2], b2_s[lane * 4 + 3]);
        }

        const ulonglong2* w2u = reinterpret_cast<const ulonglong2*>(w2);
        #pragma unroll 2
        for (int d = 0; d < Dd; d += 4) {
            float4 av[4];
            #pragma unroll
            for (int i = 0; i < 4; ++i)
                av[i] = *reinterpret_cast<const float4*>(a_s + (r0 + i) * Dd + d);
            #pragma unroll
            for (int dd = 0; dd < 4; ++dd) {
                ulonglong2 W = __ldg(w2u + (d + dd) * 32 + lane);
                #pragma unroll
                for (int i = 0; i < 4; ++i) {
                    float a = (dd == 0) ? av[i].x : (dd == 1) ? av[i].y
                            : (dd == 2) ? av[i].z : av[i].w;
                    u64 aa = bcast2(a);
                    ffma2(kv2[i][0], aa, W.x);
                    ffma2(kv2[i][1], aa, W.y);
                }
            }
        }

        // ---- RK4 stage combine (warp-private rows) ----
        float kv[4][4];
        #pragma unroll
        for (int i = 0; i < 4; ++i) {
            unpk2(kv2[i][0], kv[i][0], kv[i][1]);
            unpk2(kv2[i][1], kv[i][2], kv[i][3]);
        }

        if (s == 0) {
            #pragma unroll
            for (int i = 0; i < 4; ++i) {
                float dt = dt_s[r0 + i];
                #pragma unroll
                for (int j = 0; j < 4; ++j) {
                    int c = lane * 4 + j;
                    k1r[i][j] = kv[i][j];
                    accr[i][j] = kv[i][j];
                    arg_s[(r0 + i) * Hh + c] =
                        h_s[(r0 + i) * Hh + c] + dt * (kv[i][j] * (1.0f / 3.0f));
                }
            }
        } else if (s == 1) {
            #pragma unroll
            for (int i = 0; i < 4; ++i) {
                float dt = dt_s[r0 + i];
                #pragma unroll
                for (int j = 0; j < 4; ++j) {
                    int c = lane * 4 + j;
                    k2r[i][j] = kv[i][j];
                    accr[i][j] += 3.0f * kv[i][j];
                    arg_s[(r0 + i) * Hh + c] =
                        h_s[(r0 + i) * Hh + c] + dt * (kv[i][j] - k1r[i][j] * (1.0f / 3.0f));
                }
            }
        } else if (s == 2) {
            #pragma unroll
            for (int i = 0; i < 4; ++i) {
                float dt = dt_s[r0 + i];
                #pragma unroll
                for (int j = 0; j < 4; ++j) {
                    int c = lane * 4 + j;
                    accr[i][j] += 3.0f * kv[i][j];
                    arg_s[(r0 + i) * Hh + c] =
                        h_s[(r0 + i) * Hh + c] + dt * (k1r[i][j] - k2r[i][j] + kv[i][j]);
                }
            }
        } else {
            #pragma unroll
            for (int i = 0; i < 4; ++i) {
                float dt = dt_s[r0 + i];
                float4 o;
                float* op = reinterpret_cast<float*>(&o);
                #pragma unroll
                for (int j = 0; j < 4; ++j) {
                    int c = lane * 4 + j;
                    float hv = h_s[(r0 + i) * Hh + c];
                    float a = accr[i][j] + kv[i][j];
                    op[j] = (dt > 0.0f) ? (hv + dt * a * 0.125f) : hv;
                }
                *reinterpret_cast<float4*>(evolved + (row0 + r0 + i) * Hh + lane * 4) = o;
            }
        }
        __syncwarp();   // arg_s written before next stage's mm1 reads (same warp)
    }
}

// ---------------------------------------------------------------------------
// GRU update. lane owns column PAIRS: col = g*128 + 64*m + 2*lane (+t), so
// weights load as conflict-free LDS.64 feeding FFMA2 directly, and r/z/n for
// the same hidden index stay on the same lane.
// ---------------------------------------------------------------------------
#define GRU_SMEM_FLOATS 57344
__global__ void __launch_bounds__(NTHR, 1) gru_kernel(
    const float* __restrict__ evolved, const float* __restrict__ obs,
    const int* __restrict__ mask,
    const float* __restrict__ bih, const float* __restrict__ bhh,
    float* __restrict__ updated)
{
    extern __shared__ float sm[];
    float* w_s   = sm;              // 128x384 (192KB) — WihT then WhhT
    float* obs_s = sm + 49152;      // 32x128
    float* ev_s  = sm + 53248;      // 32x128

    const int tid  = threadIdx.x;
    const int lane = tid & 31;
    const int wrp  = tid >> 5;
    const int r0   = wrp * 4;
    const size_t row0 = (size_t)blockIdx.x * MT;

    {
        const float4* so = reinterpret_cast<const float4*>(obs + row0 * Ee);
        const float4* se = reinterpret_cast<const float4*>(evolved + row0 * Hh);
        float4* dobs = reinterpret_cast<float4*>(obs_s);
        float4* dev  = reinterpret_cast<float4*>(ev_s);
        #pragma unroll
        for (int t = 0; t < 4; ++t) {
            dobs[tid + t * NTHR] = so[tid + t * NTHR];
            dev[tid + t * NTHR]  = se[tid + t * NTHR];
        }
    }
    {
        const float4* src = reinterpret_cast<const float4*>(g_wihT);
        float4* dst = reinterpret_cast<float4*>(w_s);
        #pragma unroll
        for (int t = 0; t < 48; ++t) dst[tid + t * NTHR] = src[tid + t * NTHR];
    }
    __syncthreads();

    // accumulators: [row i][g*2+m] packed pairs
    u64 gi2[4][6], gh2[4][6];
    #pragma unroll
    for (int g = 0; g < 3; ++g)
        #pragma unroll
        for (int m = 0; m < 2; ++m) {
            int c = g * Hh + 64 * m + 2 * lane;
            u64 bi = pack2(__ldg(bih + c), __ldg(bih + c + 1));
            u64 bh = pack2(__ldg(bhh + c), __ldg(bhh + c + 1));
            #pragma unroll
            for (int i = 0; i < 4; ++i) { gi2[i][g * 2 + m] = bi; gh2[i][g * 2 + m] = bh; }
        }

    // gi = obs @ WihT + bih
    #pragma unroll 2
    for (int e = 0; e < Ee; e += 4) {
        float4 ov[4];
        #pragma unroll
        for (int i = 0; i < 4; ++i)
            ov[i] = *reinterpret_cast<const float4*>(obs_s + (r0 + i) * Ee + e);
        #pragma unroll
        for (int ee = 0; ee < 4; ++ee) {
            const float* wb = w_s + (e + ee) * G3H + 2 * lane;
            u64 W[6];
            #pragma unroll
            for (int g = 0; g < 3; ++g)
                #pragma unroll
                for (int m = 0; m < 2; ++m)
                    W[g * 2 + m] = *reinterpret_cast<const u64*>(wb + g * Hh + 64 * m);
            #pragma unroll
            for (int i = 0; i < 4; ++i) {
                float a = (ee == 0) ? ov[i].x : (ee == 1) ? ov[i].y
                        : (ee == 2) ? ov[i].z : ov[i].w;
                u64 aa = bcast2(a);
                #pragma unroll
                for (int q = 0; q < 6; ++q) ffma2(gi2[i][q], aa, W[q]);
            }
        }
    }
    __syncthreads();    // all warps done with WihT
    {
        const float4* src = reinterpret_cast<const float4*>(g_whhT);
        float4* dst = reinterpret_cast<float4*>(w_s);
        #pragma unroll
        for (int t = 0; t < 48; ++t) dst[tid + t * NTHR] = src[tid + t * NTHR];
    }
    __syncthreads();

    // gh = evolved @ WhhT + bhh
    #pragma unroll 2
    for (int e = 0; e < Hh; e += 4) {
        float4 ov[4];
        #pragma unroll
        for (int i = 0; i < 4; ++i)
            ov[i] = *reinterpret_cast<const float4*>(ev_s + (r0 + i) * Hh + e);
        #pragma unroll
        for (int ee = 0; ee < 4; ++ee) {
            const float* wb = w_s + (e + ee) * G3H + 2 * lane;
            u64 W[6];
            #pragma unroll
            for (int g = 0; g < 3; ++g)
                #pragma unroll
                for (int m = 0; m < 2; ++m)
                    W[g * 2 + m] = *reinterpret_cast<const u64*>(wb + g * Hh + 64 * m);
            #pragma unroll
            for (int i = 0; i < 4; ++i) {
                float a = (ee == 0) ? ov[i].x : (ee == 1) ? ov[i].y
                        : (ee == 2) ? ov[i].z : ov[i].w;
                u64 aa = bcast2(a);
                #pragma unroll
                for (int q = 0; q < 6; ++q) ffma2(gh2[i][q], aa, W[q]);
            }
        }
    }

    // gates + select
    #pragma unroll
    for (int i = 0; i < 4; ++i) {
        size_t grow = row0 + r0 + i;
        int msk = __ldg(mask + grow);
        #pragma unroll
        for (int m = 0; m < 2; ++m) {
            float ir0, ir1, iz0, iz1, in0, in1;
            float hr0, hr1, hz0, hz1, hn0, hn1;
            unpk2(gi2[i][0 + m], ir0, ir1);
            unpk2(gi2[i][2 + m], iz0, iz1);
            unpk2(gi2[i][4 + m], in0, in1);
            unpk2(gh2[i][0 + m], hr0, hr1);
            unpk2(gh2[i][2 + m], hz0, hz1);
            unpk2(gh2[i][4 + m], hn0, hn1);

            int hidx = 64 * m + 2 * lane;
            float2 ev = *reinterpret_cast<const float2*>(
                ev_s + (r0 + i) * Hh + hidx);

            float r0g = 1.0f / (1.0f + __expf(-(ir0 + hr0)));
            float z0g = 1.0f / (1.0f + __expf(-(iz0 + hz0)));
            float n0g = tanhf(in0 + r0g * hn0);
            float o0 = (msk > 0) ? ((1.0f - z0g) * n0g + z0g * ev.x) : ev.x;

            float r1g = 1.0f / (1.0f + __expf(-(ir1 + hr1)));
            float z1g = 1.0f / (1.0f + __expf(-(iz1 + hz1)));
            float n1g = tanhf(in1 + r1g * hn1);
            float o1 = (msk > 0) ? ((1.0f - z1g) * n1g + z1g * ev.y) : ev.y;

            float2 o; o.x = o0; o.y = o1;
            *reinterpret_cast<float2*>(updated + grow * Hh + hidx) = o;
        }
    }
}

// ---------------------------------------------------------------------------
extern "C" void kernel_launch(void* const* d_in, const int* in_sizes, int n_in,
                              void* d_out, int out_size)
{
    const float* hidden = (const float*)d_in[0];
    const float* dts    = (const float*)d_in[1];
    const float* obs    = (const float*)d_in[2];
    const int*   mask   = (const int*)d_in[3];
    const float* w1     = (const float*)d_in[4];
    const float* b1     = (const float*)d_in[5];
    const float* lnw    = (const float*)d_in[6];
    const float* lnb    = (const float*)d_in[7];
    const float* w2     = (const float*)d_in[8];
    const float* b2     = (const float*)d_in[9];
    const float* wih    = (const float*)d_in[10];
    const float* whh    = (const float*)d_in[11];
    const float* bih    = (const float*)d_in[12];
    const float* bhh    = (const float*)d_in[13];

    float* evolved = (float*)d_out;
    float* updated = evolved + (size_t)B_TOTAL * Hh;

    cudaFuncSetAttribute(evolve_kernel, cudaFuncAttributeMaxDynamicSharedMemorySize,
                         EV_SMEM_FLOATS * 4);
    cudaFuncSetAttribute(gru_kernel, cudaFuncAttributeMaxDynamicSharedMemorySize,
                         GRU_SMEM_FLOATS * 4);

    transpose_gru_kernel<<<(Ee * G3H + 255) / 256, 256>>>(wih, whh);
    evolve_kernel<<<B_TOTAL / MT, NTHR, EV_SMEM_FLOATS * 4>>>(
        hidden, dts, w1, b1, lnw, lnb, w2, b2, evolved);
    gru_kernel<<<B_TOTAL / MT, NTHR, GRU_SMEM_FLOATS * 4>>>(
        evolved, obs, mask, bih, bhh, updated);
}

// round 5
// speedup vs baseline: 1.3117x; 1.0003x over previous
#include <cuda_runtime.h>
#include <math.h>

#define B_TOTAL 131072
#define Hh 128
#define Dd 256
#define Ee 128
#define G3H 384
#define MT 32
#define NTHR 256

typedef unsigned long long u64;

__device__ __forceinline__ u64 pack2(float lo, float hi) {
    u64 r;
    asm("mov.b64 %0,{%1,%2};" : "=l"(r)
        : "r"(__float_as_uint(lo)), "r"(__float_as_uint(hi)));
    return r;
}
__device__ __forceinline__ u64 bcast2(float x) {
    u64 r;
    asm("mov.b64 %0,{%1,%1};" : "=l"(r) : "r"(__float_as_uint(x)));
    return r;
}
__device__ __forceinline__ void ffma2(u64& d, u64 a, u64 b) {
    asm("fma.rn.f32x2 %0,%1,%2,%3;" : "=l"(d) : "l"(a), "l"(b), "l"(d));
}
__device__ __forceinline__ void unpk2(u64 v, float& a, float& b) {
    unsigned lo, hi;
    asm("mov.b64 {%0,%1},%2;" : "=r"(lo), "=r"(hi) : "l"(v));
    a = __uint_as_float(lo); b = __uint_as_float(hi);
}

// Transposed GRU weights (k-major [E][3H]) — device scratch, no allocation.
__device__ float g_wihT[Ee * G3H];
__device__ float g_whhT[Hh * G3H];

__global__ void transpose_gru_kernel(const float* __restrict__ wih,
                                     const float* __restrict__ whh) {
    int idx = blockIdx.x * blockDim.x + threadIdx.x;
    if (idx < Ee * G3H) {
        int e = idx / G3H, j = idx % G3H;
        g_wihT[idx] = wih[j * Ee + e];
        g_whhT[idx] = whh[j * Hh + e];
    }
}

// ---------------------------------------------------------------------------
// evolve: one RK4 (3/8 rule) step per row. 32 rows/CTA, 8 warps, 4 rows/warp.
// Round-1 structure (warp-private smem rows, no in-loop block barriers except
// one alignment barrier per stage before mm2), FFMA2-packed inner loops.
// ---------------------------------------------------------------------------
#define EV_SMEM_FLOATS 50080
__global__ void __launch_bounds__(NTHR, 1) evolve_kernel(
    const float* __restrict__ hidden, const float* __restrict__ dts,
    const float* __restrict__ w1, const float* __restrict__ b1,
    const float* __restrict__ lnw, const float* __restrict__ lnb,
    const float* __restrict__ w2, const float* __restrict__ b2,
    float* __restrict__ evolved)
{
    extern __shared__ float sm[];
    float* w1_s  = sm;              // 32768 floats (128KB), resident
    float* h_s   = sm + 32768;      // 32x128
    float* arg_s = sm + 36864;      // 32x128
    float* a_s   = sm + 40960;      // 32x256
    float* b1_s  = sm + 49152;      // 256
    float* lnw_s = sm + 49408;      // 256
    float* lnb_s = sm + 49664;      // 256
    float* b2_s  = sm + 49920;      // 128
    float* dt_s  = sm + 50048;      // 32

    const int tid  = threadIdx.x;
    const int lane = tid & 31;
    const int wrp  = tid >> 5;
    const int r0   = wrp * 4;                       // local row base (4 rows/warp)
    const size_t row0 = (size_t)blockIdx.x * MT;

    // ---- stage weights + tile ----
    {
        const float4* src = reinterpret_cast<const float4*>(w1);
        float4* dst = reinterpret_cast<float4*>(w1_s);
        #pragma unroll
        for (int t = 0; t < 32; ++t) dst[tid + t * NTHR] = src[tid + t * NTHR];
    }
    {
        const float4* src = reinterpret_cast<const float4*>(hidden + row0 * Hh);
        float4* dh = reinterpret_cast<float4*>(h_s);
        float4* da = reinterpret_cast<float4*>(arg_s);
        #pragma unroll
        for (int t = 0; t < 4; ++t) {
            float4 v = src[tid + t * NTHR];
            dh[tid + t * NTHR] = v;
            da[tid + t * NTHR] = v;
        }
    }
    if (tid < 256) { b1_s[tid] = b1[tid]; lnw_s[tid] = lnw[tid]; lnb_s[tid] = lnb[tid]; }
    if (tid < 128) b2_s[tid] = b2[tid];
    if (tid < 32)  dt_s[tid] = fmaxf(dts[row0 + tid], 0.0f);
    __syncthreads();

    float k1r[4][4], k2r[4][4], accr[4][4];

    #pragma unroll 1
    for (int s = 0; s < 4; ++s) {
        // ---- mm1: u[4 rows][8 cols] = arg @ w1 + b1 (FFMA2-packed) ----
        u64 u2[4][4];
        #pragma unroll
        for (int i = 0; i < 4; ++i)
            #pragma unroll
            for (int p = 0; p < 4; ++p)
                u2[i][p] = pack2(b1_s[lane * 8 + 2 * p], b1_s[lane * 8 + 2 * p + 1]);

        const ulonglong2* w1u = reinterpret_cast<const ulonglong2*>(w1_s);
        #pragma unroll 2
        for (int k = 0; k < Hh; k += 4) {
            float4 av[4];
            #pragma unroll
            for (int i = 0; i < 4; ++i)
                av[i] = *reinterpret_cast<const float4*>(arg_s + (r0 + i) * Hh + k);
            #pragma unroll
            for (int kk = 0; kk < 4; ++kk) {
                ulonglong2 W0 = w1u[(k + kk) * 64 + lane * 2];
                ulonglong2 W1 = w1u[(k + kk) * 64 + lane * 2 + 1];
                #pragma unroll
                for (int i = 0; i < 4; ++i) {
                    float a = (kk == 0) ? av[i].x : (kk == 1) ? av[i].y
                            : (kk == 2) ? av[i].z : av[i].w;
                    u64 aa = bcast2(a);
                    ffma2(u2[i][0], aa, W0.x);
                    ffma2(u2[i][1], aa, W0.y);
                    ffma2(u2[i][2], aa, W1.x);
                    ffma2(u2[i][3], aa, W1.y);
                }
            }
        }

        // ---- LayerNorm + exact GELU, a -> smem ----
        #pragma unroll
        for (int i = 0; i < 4; ++i) {
            float uv[8];
            #pragma unroll
            for (int p = 0; p < 4; ++p) unpk2(u2[i][p], uv[2 * p], uv[2 * p + 1]);
            float s1 = 0.f, s2 = 0.f;
            #pragma unroll
            for (int j = 0; j < 8; ++j) { s1 += uv[j]; s2 += uv[j] * uv[j]; }
            #pragma unroll
            for (int off = 16; off >= 1; off >>= 1) {
                s1 += __shfl_xor_sync(0xffffffffu, s1, off);
                s2 += __shfl_xor_sync(0xffffffffu, s2, off);
            }
            float mu   = s1 * (1.0f / Dd);
            float var  = s2 * (1.0f / Dd) - mu * mu;
            float rstd = rsqrtf(var + 1e-5f);
            #pragma unroll
            for (int j = 0; j < 8; ++j) {
                int c = lane * 8 + j;
                float v = (uv[j] - mu) * rstd * lnw_s[c] + lnb_s[c];
                a_s[(r0 + i) * Dd + c] = v * normcdff(v);   // exact gelu
            }
        }
        // align warps so the 8-warp shared w2 L2 stream dedups in L1
        __syncthreads();

        // ---- mm2: kv[4 rows][4 cols] = a @ w2 + b2 (w2 streamed, FFMA2) ----
        u64 kv2[4][2];
        #pragma unroll
        for (int i = 0; i < 4; ++i) {
            kv2[i][0] = pack2(b2_s[lane * 4],     b2_s[lane * 4 + 1]);
            kv2[i][1] = pack2(b2_s[lane * 4 + 2], b2_s[lane * 4 + 3]);
        }

        const ulonglong2* w2u = reinterpret_cast<const ulonglong2*>(w2);
        #pragma unroll 2
        for (int d = 0; d < Dd; d += 4) {
            float4 av[4];
            #pragma unroll
            for (int i = 0; i < 4; ++i)
                av[i] = *reinterpret_cast<const float4*>(a_s + (r0 + i) * Dd + d);
            #pragma unroll
            for (int dd = 0; dd < 4; ++dd) {
                ulonglong2 W = __ldg(w2u + (d + dd) * 32 + lane);
                #pragma unroll
                for (int i = 0; i < 4; ++i) {
                    float a = (dd == 0) ? av[i].x : (dd == 1) ? av[i].y
                            : (dd == 2) ? av[i].z : av[i].w;
                    u64 aa = bcast2(a);
                    ffma2(kv2[i][0], aa, W.x);
                    ffma2(kv2[i][1], aa, W.y);
                }
            }
        }

        // ---- RK4 stage combine (warp-private rows) ----
        float kv[4][4];
        #pragma unroll
        for (int i = 0; i < 4; ++i) {
            unpk2(kv2[i][0], kv[i][0], kv[i][1]);
            unpk2(kv2[i][1], kv[i][2], kv[i][3]);
        }

        if (s == 0) {
            #pragma unroll
            for (int i = 0; i < 4; ++i) {
                float dt = dt_s[r0 + i];
                #pragma unroll
                for (int j = 0; j < 4; ++j) {
                    int c = lane * 4 + j;
                    k1r[i][j] = kv[i][j];
                    accr[i][j] = kv[i][j];
                    arg_s[(r0 + i) * Hh + c] =
                        h_s[(r0 + i) * Hh + c] + dt * (kv[i][j] * (1.0f / 3.0f));
                }
            }
        } else if (s == 1) {
            #pragma unroll
            for (int i = 0; i < 4; ++i) {
                float dt = dt_s[r0 + i];
                #pragma unroll
                for (int j = 0; j < 4; ++j) {
                    int c = lane * 4 + j;
                    k2r[i][j] = kv[i][j];
                    accr[i][j] += 3.0f * kv[i][j];
                    arg_s[(r0 + i) * Hh + c] =
                        h_s[(r0 + i) * Hh + c] + dt * (kv[i][j] - k1r[i][j] * (1.0f / 3.0f));
                }
            }
        } else if (s == 2) {
            #pragma unroll
            for (int i = 0; i < 4; ++i) {
                float dt = dt_s[r0 + i];
                #pragma unroll
                for (int j = 0; j < 4; ++j) {
                    int c = lane * 4 + j;
                    accr[i][j] += 3.0f * kv[i][j];
                    arg_s[(r0 + i) * Hh + c] =
                        h_s[(r0 + i) * Hh + c] + dt * (k1r[i][j] - k2r[i][j] + kv[i][j]);
                }
            }
        } else {
            #pragma unroll
            for (int i = 0; i < 4; ++i) {
                float dt = dt_s[r0 + i];
                float4 o;
                float* op = reinterpret_cast<float*>(&o);
                #pragma unroll
                for (int j = 0; j < 4; ++j) {
                    int c = lane * 4 + j;
                    float hv = h_s[(r0 + i) * Hh + c];
                    float a = accr[i][j] + kv[i][j];
                    op[j] = (dt > 0.0f) ? (hv + dt * a * 0.125f) : hv;
                }
                *reinterpret_cast<float4*>(evolved + (row0 + r0 + i) * Hh + lane * 4) = o;
            }
        }
        __syncwarp();   // arg_s written before next stage's mm1 reads (same warp)
    }
}

// ---------------------------------------------------------------------------
// GRU update. lane owns column PAIRS: col = g*128 + 64*m + 2*lane (+t), so
// weights load as conflict-free LDS.64 feeding FFMA2 directly, and r/z/n for
// the same hidden index stay on the same lane.
// ---------------------------------------------------------------------------
#define GRU_SMEM_FLOATS 57344
__global__ void __launch_bounds__(NTHR, 1) gru_kernel(
    const float* __restrict__ evolved, const float* __restrict__ obs,
    const int* __restrict__ mask,
    const float* __restrict__ bih, const float* __restrict__ bhh,
    float* __restrict__ updated)
{
    extern __shared__ float sm[];
    float* w_s   = sm;              // 128x384 (192KB) — WihT then WhhT
    float* obs_s = sm + 49152;      // 32x128
    float* ev_s  = sm + 53248;      // 32x128

    const int tid  = threadIdx.x;
    const int lane = tid & 31;
    const int wrp  = tid >> 5;
    const int r0   = wrp * 4;
    const size_t row0 = (size_t)blockIdx.x * MT;

    {
        const float4* so = reinterpret_cast<const float4*>(obs + row0 * Ee);
        const float4* se = reinterpret_cast<const float4*>(evolved + row0 * Hh);
        float4* dobs = reinterpret_cast<float4*>(obs_s);
        float4* dev  = reinterpret_cast<float4*>(ev_s);
        #pragma unroll
        for (int t = 0; t < 4; ++t) {
            dobs[tid + t * NTHR] = so[tid + t * NTHR];
            dev[tid + t * NTHR]  = se[tid + t * NTHR];
        }
    }
    {
        const float4* src = reinterpret_cast<const float4*>(g_wihT);
        float4* dst = reinterpret_cast<float4*>(w_s);
        #pragma unroll
        for (int t = 0; t < 48; ++t) dst[tid + t * NTHR] = src[tid + t * NTHR];
    }
    __syncthreads();

    // accumulators: [row i][g*2+m] packed pairs
    u64 gi2[4][6], gh2[4][6];
    #pragma unroll
    for (int g = 0; g < 3; ++g)
        #pragma unroll
        for (int m = 0; m < 2; ++m) {
            int c = g * Hh + 64 * m + 2 * lane;
            u64 bi = pack2(__ldg(bih + c), __ldg(bih + c + 1));
            u64 bh = pack2(__ldg(bhh + c), __ldg(bhh + c + 1));
            #pragma unroll
            for (int i = 0; i < 4; ++i) { gi2[i][g * 2 + m] = bi; gh2[i][g * 2 + m] = bh; }
        }

    // gi = obs @ WihT + bih
    #pragma unroll 2
    for (int e = 0; e < Ee; e += 4) {
        float4 ov[4];
        #pragma unroll
        for (int i = 0; i < 4; ++i)
            ov[i] = *reinterpret_cast<const float4*>(obs_s + (r0 + i) * Ee + e);
        #pragma unroll
        for (int ee = 0; ee < 4; ++ee) {
            const float* wb = w_s + (e + ee) * G3H + 2 * lane;
            u64 W[6];
            #pragma unroll
            for (int g = 0; g < 3; ++g)
                #pragma unroll
                for (int m = 0; m < 2; ++m)
                    W[g * 2 + m] = *reinterpret_cast<const u64*>(wb + g * Hh + 64 * m);
            #pragma unroll
            for (int i = 0; i < 4; ++i) {
                float a = (ee == 0) ? ov[i].x : (ee == 1) ? ov[i].y
                        : (ee == 2) ? ov[i].z : ov[i].w;
                u64 aa = bcast2(a);
                #pragma unroll
                for (int q = 0; q < 6; ++q) ffma2(gi2[i][q], aa, W[q]);
            }
        }
    }
    __syncthreads();    // all warps done with WihT
    {
        const float4* src = reinterpret_cast<const float4*>(g_whhT);
        float4* dst = reinterpret_cast<float4*>(w_s);
        #pragma unroll
        for (int t = 0; t < 48; ++t) dst[tid + t * NTHR] = src[tid + t * NTHR];
    }
    __syncthreads();

    // gh = evolved @ WhhT + bhh
    #pragma unroll 2
    for (int e = 0; e < Hh; e += 4) {
        float4 ov[4];
        #pragma unroll
        for (int i = 0; i < 4; ++i)
            ov[i] = *reinterpret_cast<const float4*>(ev_s + (r0 + i) * Hh + e);
        #pragma unroll
        for (int ee = 0; ee < 4; ++ee) {
            const float* wb = w_s + (e + ee) * G3H + 2 * lane;
            u64 W[6];
            #pragma unroll
            for (int g = 0; g < 3; ++g)
                #pragma unroll
                for (int m = 0; m < 2; ++m)
                    W[g * 2 + m] = *reinterpret_cast<const u64*>(wb + g * Hh + 64 * m);
            #pragma unroll
            for (int i = 0; i < 4; ++i) {
                float a = (ee == 0) ? ov[i].x : (ee == 1) ? ov[i].y
                        : (ee == 2) ? ov[i].z : ov[i].w;
                u64 aa = bcast2(a);
                #pragma unroll
                for (int q = 0; q < 6; ++q) ffma2(gh2[i][q], aa, W[q]);
            }
        }
    }

    // gates + select
    #pragma unroll
    for (int i = 0; i < 4; ++i) {
        size_t grow = row0 + r0 + i;
        int msk = __ldg(mask + grow);
        #pragma unroll
        for (int m = 0; m < 2; ++m) {
            float ir0, ir1, iz0, iz1, in0, in1;
            float hr0, hr1, hz0, hz1, hn0, hn1;
            unpk2(gi2[i][0 + m], ir0, ir1);
            unpk2(gi2[i][2 + m], iz0, iz1);
            unpk2(gi2[i][4 + m], in0, in1);
            unpk2(gh2[i][0 + m], hr0, hr1);
            unpk2(gh2[i][2 + m], hz0, hz1);
            unpk2(gh2[i][4 + m], hn0, hn1);

            int hidx = 64 * m + 2 * lane;
            float2 ev = *reinterpret_cast<const float2*>(
                ev_s + (r0 + i) * Hh + hidx);

            float r0g = 1.0f / (1.0f + __expf(-(ir0 + hr0)));
            float z0g = 1.0f / (1.0f + __expf(-(iz0 + hz0)));
            float n0g = tanhf(in0 + r0g * hn0);
            float o0 = (msk > 0) ? ((1.0f - z0g) * n0g + z0g * ev.x) : ev.x;

            float r1g = 1.0f / (1.0f + __expf(-(ir1 + hr1)));
            float z1g = 1.0f / (1.0f + __expf(-(iz1 + hz1)));
            float n1g = tanhf(in1 + r1g * hn1);
            float o1 = (msk > 0) ? ((1.0f - z1g) * n1g + z1g * ev.y) : ev.y;

            float2 o; o.x = o0; o.y = o1;
            *reinterpret_cast<float2*>(updated + grow * Hh + hidx) = o;
        }
    }
}

// ---------------------------------------------------------------------------
extern "C" void kernel_launch(void* const* d_in, const int* in_sizes, int n_in,
                              void* d_out, int out_size)
{
    const float* hidden = (const float*)d_in[0];
    const float* dts    = (const float*)d_in[1];
    const float* obs    = (const float*)d_in[2];
    const int*   mask   = (const int*)d_in[3];
    const float* w1     = (const float*)d_in[4];
    const float* b1     = (const float*)d_in[5];
    const float* lnw    = (const float*)d_in[6];
    const float* lnb    = (const float*)d_in[7];
    const float* w2     = (const float*)d_in[8];
    const float* b2     = (const float*)d_in[9];
    const float* wih    = (const float*)d_in[10];
    const float* whh    = (const float*)d_in[11];
    const float* bih    = (const float*)d_in[12];
    const float* bhh    = (const float*)d_in[13];

    float* evolved = (float*)d_out;
    float* updated = evolved + (size_t)B_TOTAL * Hh;

    cudaFuncSetAttribute(evolve_kernel, cudaFuncAttributeMaxDynamicSharedMemorySize,
                         EV_SMEM_FLOATS * 4);
    cudaFuncSetAttribute(gru_kernel, cudaFuncAttributeMaxDynamicSharedMemorySize,
                         GRU_SMEM_FLOATS * 4);

    transpose_gru_kernel<<<(Ee * G3H + 255) / 256, 256>>>(wih, whh);
    evolve_kernel<<<B_TOTAL / MT, NTHR, EV_SMEM_FLOATS * 4>>>(
        hidden, dts, w1, b1, lnw, lnb, w2, b2, evolved);
    gru_kernel<<<B_TOTAL / MT, NTHR, GRU_SMEM_FLOATS * 4>>>(
        evolved, obs, mask, bih, bhh, updated);
}

// round 6
// speedup vs baseline: 1.3117x; 1.0000x over previous
#include <cuda_runtime.h>
#include <math.h>

#define B_TOTAL 131072
#define Hh 128
#define Dd 256
#define Ee 128
#define G3H 384
#define MT 32
#define NTHR 256

typedef unsigned long long u64;

__device__ __forceinline__ u64 pack2(float lo, float hi) {
    u64 r;
    asm("mov.b64 %0,{%1,%2};" : "=l"(r)
        : "r"(__float_as_uint(lo)), "r"(__float_as_uint(hi)));
    return r;
}
__device__ __forceinline__ u64 bcast2(float x) {
    u64 r;
    asm("mov.b64 %0,{%1,%1};" : "=l"(r) : "r"(__float_as_uint(x)));
    return r;
}
__device__ __forceinline__ void ffma2(u64& d, u64 a, u64 b) {
    asm("fma.rn.f32x2 %0,%1,%2,%3;" : "=l"(d) : "l"(a), "l"(b), "l"(d));
}
__device__ __forceinline__ void unpk2(u64 v, float& a, float& b) {
    unsigned lo, hi;
    asm("mov.b64 {%0,%1},%2;" : "=r"(lo), "=r"(hi) : "l"(v));
    a = __uint_as_float(lo); b = __uint_as_float(hi);
}

// Transposed GRU weights (k-major [E][3H]) — device scratch, no allocation.
__device__ float g_wihT[Ee * G3H];
__device__ float g_whhT[Hh * G3H];

__global__ void transpose_gru_kernel(const float* __restrict__ wih,
                                     const float* __restrict__ whh) {
    int idx = blockIdx.x * blockDim.x + threadIdx.x;
    if (idx < Ee * G3H) {
        int e = idx / G3H, j = idx % G3H;
        g_wihT[idx] = wih[j * Ee + e];
        g_whhT[idx] = whh[j * Hh + e];
    }
}

// ---------------------------------------------------------------------------
// evolve: one RK4 (3/8 rule) step per row. 32 rows/CTA, 8 warps, 4 rows/warp.
// Round-1 structure (warp-private smem rows, no in-loop block barriers except
// one alignment barrier per stage before mm2), FFMA2-packed inner loops.
// ---------------------------------------------------------------------------
#define EV_SMEM_FLOATS 50080
__global__ void __launch_bounds__(NTHR, 1) evolve_kernel(
    const float* __restrict__ hidden, const float* __restrict__ dts,
    const float* __restrict__ w1, const float* __restrict__ b1,
    const float* __restrict__ lnw, const float* __restrict__ lnb,
    const float* __restrict__ w2, const float* __restrict__ b2,
    float* __restrict__ evolved)
{
    extern __shared__ float sm[];
    float* w1_s  = sm;              // 32768 floats (128KB), resident
    float* h_s   = sm + 32768;      // 32x128
    float* arg_s = sm + 36864;      // 32x128
    float* a_s   = sm + 40960;      // 32x256
    float* b1_s  = sm + 49152;      // 256
    float* lnw_s = sm + 49408;      // 256
    float* lnb_s = sm + 49664;      // 256
    float* b2_s  = sm + 49920;      // 128
    float* dt_s  = sm + 50048;      // 32

    const int tid  = threadIdx.x;
    const int lane = tid & 31;
    const int wrp  = tid >> 5;
    const int r0   = wrp * 4;                       // local row base (4 rows/warp)
    const size_t row0 = (size_t)blockIdx.x * MT;

    // ---- stage weights + tile ----
    {
        const float4* src = reinterpret_cast<const float4*>(w1);
        float4* dst = reinterpret_cast<float4*>(w1_s);
        #pragma unroll
        for (int t = 0; t < 32; ++t) dst[tid + t * NTHR] = src[tid + t * NTHR];
    }
    {
        const float4* src = reinterpret_cast<const float4*>(hidden + row0 * Hh);
        float4* dh = reinterpret_cast<float4*>(h_s);
        float4* da = reinterpret_cast<float4*>(arg_s);
        #pragma unroll
        for (int t = 0; t < 4; ++t) {
            float4 v = src[tid + t * NTHR];
            dh[tid + t * NTHR] = v;
            da[tid + t * NTHR] = v;
        }
    }
    if (tid < 256) { b1_s[tid] = b1[tid]; lnw_s[tid] = lnw[tid]; lnb_s[tid] = lnb[tid]; }
    if (tid < 128) b2_s[tid] = b2[tid];
    if (tid < 32)  dt_s[tid] = fmaxf(dts[row0 + tid], 0.0f);
    __syncthreads();

    float k1r[4][4], k2r[4][4], accr[4][4];

    #pragma unroll 1
    for (int s = 0; s < 4; ++s) {
        // ---- mm1: u[4 rows][8 cols] = arg @ w1 + b1 (FFMA2-packed) ----
        u64 u2[4][4];
        #pragma unroll
        for (int i = 0; i < 4; ++i)
            #pragma unroll
            for (int p = 0; p < 4; ++p)
                u2[i][p] = pack2(b1_s[lane * 8 + 2 * p], b1_s[lane * 8 + 2 * p + 1]);

        const ulonglong2* w1u = reinterpret_cast<const ulonglong2*>(w1_s);
        #pragma unroll 2
        for (int k = 0; k < Hh; k += 4) {
            float4 av[4];
            #pragma unroll
            for (int i = 0; i < 4; ++i)
                av[i] = *reinterpret_cast<const float4*>(arg_s + (r0 + i) * Hh + k);
            #pragma unroll
            for (int kk = 0; kk < 4; ++kk) {
                ulonglong2 W0 = w1u[(k + kk) * 64 + lane * 2];
                ulonglong2 W1 = w1u[(k + kk) * 64 + lane * 2 + 1];
                #pragma unroll
                for (int i = 0; i < 4; ++i) {
                    float a = (kk == 0) ? av[i].x : (kk == 1) ? av[i].y
                            : (kk == 2) ? av[i].z : av[i].w;
                    u64 aa = bcast2(a);
                    ffma2(u2[i][0], aa, W0.x);
                    ffma2(u2[i][1], aa, W0.y);
                    ffma2(u2[i][2], aa, W1.x);
                    ffma2(u2[i][3], aa, W1.y);
                }
            }
        }

        // ---- LayerNorm + exact GELU, a -> smem ----
        #pragma unroll
        for (int i = 0; i < 4; ++i) {
            float uv[8];
            #pragma unroll
            for (int p = 0; p < 4; ++p) unpk2(u2[i][p], uv[2 * p], uv[2 * p + 1]);
            float s1 = 0.f, s2 = 0.f;
            #pragma unroll
            for (int j = 0; j < 8; ++j) { s1 += uv[j]; s2 += uv[j] * uv[j]; }
            #pragma unroll
            for (int off = 16; off >= 1; off >>= 1) {
                s1 += __shfl_xor_sync(0xffffffffu, s1, off);
                s2 += __shfl_xor_sync(0xffffffffu, s2, off);
            }
            float mu   = s1 * (1.0f / Dd);
            float var  = s2 * (1.0f / Dd) - mu * mu;
            float rstd = rsqrtf(var + 1e-5f);
            #pragma unroll
            for (int j = 0; j < 8; ++j) {
                int c = lane * 8 + j;
                float v = (uv[j] - mu) * rstd * lnw_s[c] + lnb_s[c];
                a_s[(r0 + i) * Dd + c] = v * normcdff(v);   // exact gelu
            }
        }
        // align warps so the 8-warp shared w2 L2 stream dedups in L1
        __syncthreads();

        // ---- mm2: kv[4 rows][4 cols] = a @ w2 + b2 (w2 streamed, FFMA2) ----
        u64 kv2[4][2];
        #pragma unroll
        for (int i = 0; i < 4; ++i) {
            kv2[i][0] = pack2(b2_s[lane * 4],     b2_s[lane * 4 + 1]);
            kv2[i][1] = pack2(b2_s[lane * 4 + 2], b2_s[lane * 4 + 3]);
        }

        const ulonglong2* w2u = reinterpret_cast<const ulonglong2*>(w2);
        #pragma unroll 2
        for (int d = 0; d < Dd; d += 4) {
            float4 av[4];
            #pragma unroll
            for (int i = 0; i < 4; ++i)
                av[i] = *reinterpret_cast<const float4*>(a_s + (r0 + i) * Dd + d);
            #pragma unroll
            for (int dd = 0; dd < 4; ++dd) {
                ulonglong2 W = __ldg(w2u + (d + dd) * 32 + lane);
                #pragma unroll
                for (int i = 0; i < 4; ++i) {
                    float a = (dd == 0) ? av[i].x : (dd == 1) ? av[i].y
                            : (dd == 2) ? av[i].z : av[i].w;
                    u64 aa = bcast2(a);
                    ffma2(kv2[i][0], aa, W.x);
                    ffma2(kv2[i][1], aa, W.y);
                }
            }
        }

        // ---- RK4 stage combine (warp-private rows) ----
        float kv[4][4];
        #pragma unroll
        for (int i = 0; i < 4; ++i) {
            unpk2(kv2[i][0], kv[i][0], kv[i][1]);
            unpk2(kv2[i][1], kv[i][2], kv[i][3]);
        }

        if (s == 0) {
            #pragma unroll
            for (int i = 0; i < 4; ++i) {
                float dt = dt_s[r0 + i];
                #pragma unroll
                for (int j = 0; j < 4; ++j) {
                    int c = lane * 4 + j;
                    k1r[i][j] = kv[i][j];
                    accr[i][j] = kv[i][j];
                    arg_s[(r0 + i) * Hh + c] =
                        h_s[(r0 + i) * Hh + c] + dt * (kv[i][j] * (1.0f / 3.0f));
                }
            }
        } else if (s == 1) {
            #pragma unroll
            for (int i = 0; i < 4; ++i) {
                float dt = dt_s[r0 + i];
                #pragma unroll
                for (int j = 0; j < 4; ++j) {
                    int c = lane * 4 + j;
                    k2r[i][j] = kv[i][j];
                    accr[i][j] += 3.0f * kv[i][j];
                    arg_s[(r0 + i) * Hh + c] =
                        h_s[(r0 + i) * Hh + c] + dt * (kv[i][j] - k1r[i][j] * (1.0f / 3.0f));
                }
            }
        } else if (s == 2) {
            #pragma unroll
            for (int i = 0; i < 4; ++i) {
                float dt = dt_s[r0 + i];
                #pragma unroll
                for (int j = 0; j < 4; ++j) {
                    int c = lane * 4 + j;
                    accr[i][j] += 3.0f * kv[i][j];
                    arg_s[(r0 + i) * Hh + c] =
                        h_s[(r0 + i) * Hh + c] + dt * (k1r[i][j] - k2r[i][j] + kv[i][j]);
                }
            }
        } else {
            #pragma unroll
            for (int i = 0; i < 4; ++i) {
                float dt = dt_s[r0 + i];
                float4 o;
                float* op = reinterpret_cast<float*>(&o);
                #pragma unroll
                for (int j = 0; j < 4; ++j) {
                    int c = lane * 4 + j;
                    float hv = h_s[(r0 + i) * Hh + c];
                    float a = accr[i][j] + kv[i][j];
                    op[j] = (dt > 0.0f) ? (hv + dt * a * 0.125f) : hv;
                }
                *reinterpret_cast<float4*>(evolved + (row0 + r0 + i) * Hh + lane * 4) = o;
            }
        }
        __syncwarp();   // arg_s written before next stage's mm1 reads (same warp)
    }
}

// ---------------------------------------------------------------------------
// GRU update. lane owns column PAIRS: col = g*128 + 64*m + 2*lane (+t), so
// weights load as conflict-free LDS.64 feeding FFMA2 directly, and r/z/n for
// the same hidden index stay on the same lane.
// ---------------------------------------------------------------------------
#define GRU_SMEM_FLOATS 57344
__global__ void __launch_bounds__(NTHR, 1) gru_kernel(
    const float* __restrict__ evolved, const float* __restrict__ obs,
    const int* __restrict__ mask,
    const float* __restrict__ bih, const float* __restrict__ bhh,
    float* __restrict__ updated)
{
    extern __shared__ float sm[];
    float* w_s   = sm;              // 128x384 (192KB) — WihT then WhhT
    float* obs_s = sm + 49152;      // 32x128
    float* ev_s  = sm + 53248;      // 32x128

    const int tid  = threadIdx.x;
    const int lane = tid & 31;
    const int wrp  = tid >> 5;
    const int r0   = wrp * 4;
    const size_t row0 = (size_t)blockIdx.x * MT;

    {
        const float4* so = reinterpret_cast<const float4*>(obs + row0 * Ee);
        const float4* se = reinterpret_cast<const float4*>(evolved + row0 * Hh);
        float4* dobs = reinterpret_cast<float4*>(obs_s);
        float4* dev  = reinterpret_cast<float4*>(ev_s);
        #pragma unroll
        for (int t = 0; t < 4; ++t) {
            dobs[tid + t * NTHR] = so[tid + t * NTHR];
            dev[tid + t * NTHR]  = se[tid + t * NTHR];
        }
    }
    {
        const float4* src = reinterpret_cast<const float4*>(g_wihT);
        float4* dst = reinterpret_cast<float4*>(w_s);
        #pragma unroll
        for (int t = 0; t < 48; ++t) dst[tid + t * NTHR] = src[tid + t * NTHR];
    }
    __syncthreads();

    // accumulators: [row i][g*2+m] packed pairs
    u64 gi2[4][6], gh2[4][6];
    #pragma unroll
    for (int g = 0; g < 3; ++g)
        #pragma unroll
        for (int m = 0; m < 2; ++m) {
            int c = g * Hh + 64 * m + 2 * lane;
            u64 bi = pack2(__ldg(bih + c), __ldg(bih + c + 1));
            u64 bh = pack2(__ldg(bhh + c), __ldg(bhh + c + 1));
            #pragma unroll
            for (int i = 0; i < 4; ++i) { gi2[i][g * 2 + m] = bi; gh2[i][g * 2 + m] = bh; }
        }

    // gi = obs @ WihT + bih
    #pragma unroll 2
    for (int e = 0; e < Ee; e += 4) {
        float4 ov[4];
        #pragma unroll
        for (int i = 0; i < 4; ++i)
            ov[i] = *reinterpret_cast<const float4*>(obs_s + (r0 + i) * Ee + e);
        #pragma unroll
        for (int ee = 0; ee < 4; ++ee) {
            const float* wb = w_s + (e + ee) * G3H + 2 * lane;
            u64 W[6];
            #pragma unroll
            for (int g = 0; g < 3; ++g)
                #pragma unroll
                for (int m = 0; m < 2; ++m)
                    W[g * 2 + m] = *reinterpret_cast<const u64*>(wb + g * Hh + 64 * m);
            #pragma unroll
            for (int i = 0; i < 4; ++i) {
                float a = (ee == 0) ? ov[i].x : (ee == 1) ? ov[i].y
                        : (ee == 2) ? ov[i].z : ov[i].w;
                u64 aa = bcast2(a);
                #pragma unroll
                for (int q = 0; q < 6; ++q) ffma2(gi2[i][q], aa, W[q]);
            }
        }
    }
    __syncthreads();    // all warps done with WihT
    {
        const float4* src = reinterpret_cast<const float4*>(g_whhT);
        float4* dst = reinterpret_cast<float4*>(w_s);
        #pragma unroll
        for (int t = 0; t < 48; ++t) dst[tid + t * NTHR] = src[tid + t * NTHR];
    }
    __syncthreads();

    // gh = evolved @ WhhT + bhh
    #pragma unroll 2
    for (int e = 0; e < Hh; e += 4) {
        float4 ov[4];
        #pragma unroll
        for (int i = 0; i < 4; ++i)
            ov[i] = *reinterpret_cast<const float4*>(ev_s + (r0 + i) * Hh + e);
        #pragma unroll
        for (int ee = 0; ee < 4; ++ee) {
            const float* wb = w_s + (e + ee) * G3H + 2 * lane;
            u64 W[6];
            #pragma unroll
            for (int g = 0; g < 3; ++g)
                #pragma unroll
                for (int m = 0; m < 2; ++m)
                    W[g * 2 + m] = *reinterpret_cast<const u64*>(wb + g * Hh + 64 * m);
            #pragma unroll
            for (int i = 0; i < 4; ++i) {
                float a = (ee == 0) ? ov[i].x : (ee == 1) ? ov[i].y
                        : (ee == 2) ? ov[i].z : ov[i].w;
                u64 aa = bcast2(a);
                #pragma unroll
                for (int q = 0; q < 6; ++q) ffma2(gh2[i][q], aa, W[q]);
            }
        }
    }

    // gates + select
    #pragma unroll
    for (int i = 0; i < 4; ++i) {
        size_t grow = row0 + r0 + i;
        int msk = __ldg(mask + grow);
        #pragma unroll
        for (int m = 0; m < 2; ++m) {
            float ir0, ir1, iz0, iz1, in0, in1;
            float hr0, hr1, hz0, hz1, hn0, hn1;
            unpk2(gi2[i][0 + m], ir0, ir1);
            unpk2(gi2[i][2 + m], iz0, iz1);
            unpk2(gi2[i][4 + m], in0, in1);
            unpk2(gh2[i][0 + m], hr0, hr1);
            unpk2(gh2[i][2 + m], hz0, hz1);
            unpk2(gh2[i][4 + m], hn0, hn1);

            int hidx = 64 * m + 2 * lane;
            float2 ev = *reinterpret_cast<const float2*>(
                ev_s + (r0 + i) * Hh + hidx);

            float r0g = 1.0f / (1.0f + __expf(-(ir0 + hr0)));
            float z0g = 1.0f / (1.0f + __expf(-(iz0 + hz0)));
            float n0g = tanhf(in0 + r0g * hn0);
            float o0 = (msk > 0) ? ((1.0f - z0g) * n0g + z0g * ev.x) : ev.x;

            float r1g = 1.0f / (1.0f + __expf(-(ir1 + hr1)));
            float z1g = 1.0f / (1.0f + __expf(-(iz1 + hz1)));
            float n1g = tanhf(in1 + r1g * hn1);
            float o1 = (msk > 0) ? ((1.0f - z1g) * n1g + z1g * ev.y) : ev.y;

            float2 o; o.x = o0; o.y = o1;
            *reinterpret_cast<float2*>(updated + grow * Hh + hidx) = o;
        }
    }
}

// ---------------------------------------------------------------------------
extern "C" void kernel_launch(void* const* d_in, const int* in_sizes, int n_in,
                              void* d_out, int out_size)
{
    const float* hidden = (const float*)d_in[0];
    const float* dts    = (const float*)d_in[1];
    const float* obs    = (const float*)d_in[2];
    const int*   mask   = (const int*)d_in[3];
    const float* w1     = (const float*)d_in[4];
    const float* b1     = (const float*)d_in[5];
    const float* lnw    = (const float*)d_in[6];
    const float* lnb    = (const float*)d_in[7];
    const float* w2     = (const float*)d_in[8];
    const float* b2     = (const float*)d_in[9];
    const float* wih    = (const float*)d_in[10];
    const float* whh    = (const float*)d_in[11];
    const float* bih    = (const float*)d_in[12];
    const float* bhh    = (const float*)d_in[13];

    float* evolved = (float*)d_out;
    float* updated = evolved + (size_t)B_TOTAL * Hh;

    cudaFuncSetAttribute(evolve_kernel, cudaFuncAttributeMaxDynamicSharedMemorySize,
                         EV_SMEM_FLOATS * 4);
    cudaFuncSetAttribute(gru_kernel, cudaFuncAttributeMaxDynamicSharedMemorySize,
                         GRU_SMEM_FLOATS * 4);

    transpose_gru_kernel<<<(Ee * G3H + 255) / 256, 256>>>(wih, whh);
    evolve_kernel<<<B_TOTAL / MT, NTHR, EV_SMEM_FLOATS * 4>>>(
        hidden, dts, w1, b1, lnw, lnb, w2, b2, evolved);
    gru_kernel<<<B_TOTAL / MT, NTHR, GRU_SMEM_FLOATS * 4>>>(
        evolved, obs, mask, bih, bhh, updated);
}